// round 7
// baseline (speedup 1.0000x reference)
#include <cuda_runtime.h>
#include <math.h>

#define N_NODES 8192
#define F_DIM   64
#define H_DIM   128
#define R_DIM   3
#define DEG     32
#define K_TOP   32
#define E_EDGES (N_NODES*DEG)
#define TEMP    0.3f
#define NEG     0.2f
#define EPS_LN  1e-5f
#define THRESH  1e-6f

#define A1_BLOCKS 256

typedef unsigned long long ull;

// deterministic scratch (no atomics)
__device__ float g_part_gs[A1_BLOCKS * F_DIM];
__device__ float g_part_cont[A1_BLOCKS];
__device__ float g_regime[R_DIM];
__device__ float g_amp;

// ---------------------------------------------------------------------------
// f32x2 helpers (sm_103a packed fp32 math; bitwise identical to scalar FFMA)
__device__ __forceinline__ ull pk2(float x, float y) {
    ull r;
    asm("mov.b64 %0, {%1, %2};" : "=l"(r) : "f"(x), "f"(y));
    return r;
}
__device__ __forceinline__ void upk2(ull v, float& x, float& y) {
    asm("mov.b64 {%0, %1}, %2;" : "=f"(x), "=f"(y) : "l"(v));
}
__device__ __forceinline__ void fma2(ull& d, ull a, ull b) {
    asm("fma.rn.f32x2 %0, %1, %2, %0;" : "+l"(d) : "l"(a), "l"(b));
}
// load 16B of read-only weights as two packed f32x2 operands
__device__ __forceinline__ void ldg2x2(const float* p, ull& a, ull& b) {
    asm("ld.global.nc.v2.b64 {%0, %1}, [%2];" : "=l"(a), "=l"(b) : "l"(p));
}

// ---------------------------------------------------------------------------
// A1: per-block (32 nodes) partial column sums of x, and partial contagion sums
__global__ void kA1(const float* __restrict__ x,
                    const float* __restrict__ Wc1, const float* __restrict__ bc1,
                    const float* __restrict__ Wc2, const float* __restrict__ bc2) {
    __shared__ float xs[32][64];
    __shared__ float colsum[4][64];
    __shared__ float cwarp[8];
    int t = threadIdx.x, b = blockIdx.x;
    int base = b * 32;
    for (int idx = t; idx < 32 * 64; idx += 256)
        xs[idx >> 6][idx & 63] = x[base * 64 + idx];
    __syncthreads();
    {
        int col = t & 63, g = t >> 6;
        float s = 0.f;
        #pragma unroll
        for (int rr = 0; rr < 8; rr++) s += xs[g * 8 + rr][col];
        colsum[g][col] = s;
    }
    // contagion: warp w -> nodes w*4..w*4+3, weight loads shared across 4 nodes
    int w = t >> 5, l = t & 31;
    float a[4][4];
    #pragma unroll
    for (int q = 0; q < 4; q++) {
        a[q][0] = bc1[l]; a[q][1] = bc1[l + 32];
        a[q][2] = bc1[l + 64]; a[q][3] = bc1[l + 96];
    }
    #pragma unroll 4
    for (int d = 0; d < 64; d++) {
        const float* Wd = Wc1 + d * 128;
        float w0 = Wd[l], w1 = Wd[l + 32], w2 = Wd[l + 64], w3 = Wd[l + 96];
        #pragma unroll
        for (int q = 0; q < 4; q++) {
            float xv = xs[w * 4 + q][d];
            a[q][0] += xv * w0; a[q][1] += xv * w1;
            a[q][2] += xv * w2; a[q][3] += xv * w3;
        }
    }
    float csum = 0.f;
    #pragma unroll
    for (int q = 0; q < 4; q++) {
        float s = fmaxf(a[q][0], 0.f) * Wc2[l]      + fmaxf(a[q][1], 0.f) * Wc2[l + 32]
                + fmaxf(a[q][2], 0.f) * Wc2[l + 64] + fmaxf(a[q][3], 0.f) * Wc2[l + 96];
        #pragma unroll
        for (int off = 16; off; off >>= 1) s += __shfl_xor_sync(0xffffffffu, s, off);
        if (l == 0) csum += 1.f / (1.f + expf(-(s + bc2[0])));
    }
    if (l == 0) cwarp[w] = csum;
    __syncthreads();
    if (t < 64) g_part_gs[b * 64 + t] = colsum[0][t] + colsum[1][t] + colsum[2][t] + colsum[3][t];
    if (t == 0) {
        float s = 0.f;
        for (int i = 0; i < 8; i++) s += cwarp[i];
        g_part_cont[b] = s;
    }
}

// ---------------------------------------------------------------------------
// A2: finalize gs mean, regime probs, contagion amp
__global__ void kA2(const float* __restrict__ Wr1, const float* __restrict__ br1,
                    const float* __restrict__ Wr2, const float* __restrict__ br2) {
    __shared__ float gs[64];
    __shared__ float hr[128];
    int t = threadIdx.x;
    if (t < 64) {
        float s = 0.f;
        for (int b = 0; b < A1_BLOCKS; b++) s += g_part_gs[b * 64 + t];
        gs[t] = s / (float)N_NODES;
    }
    __syncthreads();
    {
        float a = br1[t];
        for (int d = 0; d < 64; d++) a += gs[d] * Wr1[d * 128 + t];
        hr[t] = fmaxf(a, 0.f);
    }
    __syncthreads();
    if (t == 0) {
        float lg[3];
        for (int r = 0; r < 3; r++) {
            float a = br2[r];
            for (int h = 0; h < 128; h++) a += hr[h] * Wr2[h * 3 + r];
            lg[r] = a;
        }
        float m = fmaxf(lg[0], fmaxf(lg[1], lg[2]));
        float e0 = expf(lg[0] - m), e1 = expf(lg[1] - m), e2 = expf(lg[2] - m);
        float s = e0 + e1 + e2;
        g_regime[0] = e0 / s; g_regime[1] = e1 / s; g_regime[2] = e2 / s;
        float c = 0.f;
        for (int b = 0; b < A1_BLOCKS; b++) c += g_part_cont[b];
        g_amp = 1.f + 0.5f * (c / (float)N_NODES);
    }
}

// ---------------------------------------------------------------------------
// Main per-row kernel. Shared layout (float offsets):
//   [0:64)      sx            [64:96)   tg (int)     [96:192)  sea
//   [192:448)   base_f (fused 256 cols: 0..127 Ws1-side, 128..255 Wp-side)
//   [448:480)   raw           [480:512) sc           [512:608) gpart[3][32]
//   [608:4704)  A2  : 32x64 duplicated pairs (a,a) as b64  (16 KB)
//   [4704:12896) P2 : 32x128 duplicated pairs (p,p) as b64 (32 KB)
#define SM_A2    608
#define SM_P2    4704
#define SM_TOTAL 12896
#define SMEM_B_BYTES (SM_TOTAL * 4)

__global__ void __launch_bounds__(256, 4) kB(
    const float* __restrict__ x, const void* __restrict__ eidx, const float* __restrict__ ea,
    const float* __restrict__ Ws1, const float* __restrict__ bs1,
    const float* __restrict__ ln_g, const float* __restrict__ ln_b,
    const float* __restrict__ Ws2, const float* __restrict__ bs2,
    const float* __restrict__ Wp,  const float* __restrict__ bp,
    const float* __restrict__ Wg1, const float* __restrict__ bg1,
    const float* __restrict__ Wg2, const float* __restrict__ bg2,
    float* __restrict__ out, int write_idx) {

    extern __shared__ float smf[];
    float* sx     = smf;
    int*   tg     = (int*)(smf + 64);
    float* sea    = smf + 96;
    float* base_f = smf + 192;
    float* raw    = smf + 448;
    float* sc     = smf + 480;
    float* gpart  = smf + 512;
    ull*   A2u    = (ull*)(smf + SM_A2);
    ull*   P2u    = (ull*)(smf + SM_P2);

    int t = threadIdx.x;
    int r = blockIdx.x;

    // ---- phase 0a: small loads -----------------------------------------
    if (t < 16) ((float4*)sx)[t] = ((const float4*)(x + r * 64))[t];
    if (t >= 64 && t < 96) {
        int j = t - 64;
        int e = r * DEG + j;
        const long long* p64 = (const long long*)eidx;
        int tgv;
        if (p64[32] == 1LL) tgv = (int)p64[E_EDGES + e];
        else                tgv = ((const int*)eidx)[E_EDGES + e];
        tg[j] = tgv;
    }
    if (t >= 96 && t < 192) sea[t - 96] = ea[r * 96 + (t - 96)];
    __syncthreads();

    // ---- phase 0b: base_f (t<64) | gather A2 duplicated (t>=64) ---------
    if (t < 64) {
        int c0 = 4 * t;  // fused column
        const float* W = (t < 32) ? (Ws1 + c0) : (Wp + (c0 - 128));
        float4 acc = (t < 32) ? *(const float4*)(bs1 + c0) : *(const float4*)(bp + (c0 - 128));
        #pragma unroll 4
        for (int d = 0; d < 64; d++) {
            float4 w4 = *(const float4*)(W + d * 128);
            float a = sx[d];
            acc.x += a * w4.x; acc.y += a * w4.y; acc.z += a * w4.z; acc.w += a * w4.w;
        }
        ((float4*)base_f)[t] = acc;
    } else {
        const float4* x4 = (const float4*)x;
        for (int idx = t - 64; idx < 512; idx += 192) {
            int row = idx >> 4, d4 = idx & 15;
            float4 v = x4[tg[row] * 16 + d4];
            ull* dst = A2u + row * 64 + d4 * 4;
            dst[0] = pk2(v.x, v.x); dst[1] = pk2(v.y, v.y);
            dst[2] = pk2(v.z, v.z); dst[3] = pk2(v.w, v.w);
        }
    }
    __syncthreads();

    // ---- phase 1: fused [32 x 256] GEMM (H | P), warp = 4 rows ----------
    // lane l: 8 fused columns 8l..8l+7 (l<16 -> H via Ws1, l>=16 -> P via Wp)
    int w5 = t >> 5, l = t & 31;
    int j0 = w5 * 4;
    bool isH = l < 16;
    const float* Wb = isH ? (Ws1 + 8 * l) : (Wp + 8 * (l - 16));
    ull acc2[4][4];
    {
        const ull* bf = (const ull*)(base_f + 8 * l);
        #pragma unroll
        for (int jj = 0; jj < 4; jj++) {
            acc2[jj][0] = bf[0]; acc2[jj][1] = bf[1];
            acc2[jj][2] = bf[2]; acc2[jj][3] = bf[3];
        }
    }
    {
        // tgt-node half of the fused weight: rows 64..127
        const float* Wtgt = Wb + 64 * 128;
        const ull* Arow = A2u + j0 * 64;
        #pragma unroll 4
        for (int d = 0; d < 64; d++) {
            ull w0, w1, w2, w3;
            ldg2x2(Wtgt + d * 128, w0, w1);
            ldg2x2(Wtgt + d * 128 + 4, w2, w3);
            #pragma unroll
            for (int jj = 0; jj < 4; jj++) {
                ull a = Arow[jj * 64 + d];
                fma2(acc2[jj][0], a, w0); fma2(acc2[jj][1], a, w1);
                fma2(acc2[jj][2], a, w2); fma2(acc2[jj][3], a, w3);
            }
        }
        // edge-attr tail (rows 128..130 of the fused weight)
        #pragma unroll
        for (int k = 0; k < 3; k++) {
            ull e0, e1, e2, e3;
            ldg2x2(Wb + (128 + k) * 128, e0, e1);
            ldg2x2(Wb + (128 + k) * 128 + 4, e2, e3);
            #pragma unroll
            for (int jj = 0; jj < 4; jj++) {
                float sv = sea[(j0 + jj) * 3 + k];
                ull sp = pk2(sv, sv);
                fma2(acc2[jj][0], sp, e0); fma2(acc2[jj][1], sp, e1);
                fma2(acc2[jj][2], sp, e2); fma2(acc2[jj][3], sp, e3);
            }
        }
    }
    // ---- phase 1 epilogue: H lanes -> fused LayerNorm+LeakyReLU+score ---
    if (isH) {
        int c0 = 8 * l;
        float4 g0 = *(const float4*)(ln_g + c0), g1 = *(const float4*)(ln_g + c0 + 4);
        float4 b0 = *(const float4*)(ln_b + c0), b1 = *(const float4*)(ln_b + c0 + 4);
        float4 s0 = *(const float4*)(Ws2 + c0),  s1 = *(const float4*)(Ws2 + c0 + 4);
        float gg[8] = {g0.x,g0.y,g0.z,g0.w,g1.x,g1.y,g1.z,g1.w};
        float bb[8] = {b0.x,b0.y,b0.z,b0.w,b1.x,b1.y,b1.z,b1.w};
        float ww[8] = {s0.x,s0.y,s0.z,s0.w,s1.x,s1.y,s1.z,s1.w};
        float bias2 = bs2[0];
        #pragma unroll
        for (int jj = 0; jj < 4; jj++) {
            float v[8];
            upk2(acc2[jj][0], v[0], v[1]); upk2(acc2[jj][1], v[2], v[3]);
            upk2(acc2[jj][2], v[4], v[5]); upk2(acc2[jj][3], v[6], v[7]);
            float s = 0.f, ss = 0.f;
            #pragma unroll
            for (int i = 0; i < 8; i++) { s += v[i]; ss += v[i] * v[i]; }
            #pragma unroll
            for (int off = 1; off <= 8; off <<= 1) {
                s  += __shfl_xor_sync(0x0000ffffu, s, off);
                ss += __shfl_xor_sync(0x0000ffffu, ss, off);
            }
            float mu  = s * (1.f / 128.f);
            float var = fmaxf(ss * (1.f / 128.f) - mu * mu, 0.f);
            float inv = rsqrtf(var + EPS_LN);
            float contrib = 0.f;
            #pragma unroll
            for (int i = 0; i < 8; i++) {
                float hn = (v[i] - mu) * inv * gg[i] + bb[i];
                hn = hn >= 0.f ? hn : NEG * hn;
                contrib += hn * ww[i];
            }
            #pragma unroll
            for (int off = 1; off <= 8; off <<= 1)
                contrib += __shfl_xor_sync(0x0000ffffu, contrib, off);
            if (l == 0) raw[j0 + jj] = contrib + bias2;
        }
    } else {
        // P lanes: relu + duplicated store to P2
        int c0p = (l - 16) * 8;
        #pragma unroll
        for (int jj = 0; jj < 4; jj++) {
            float v[8];
            upk2(acc2[jj][0], v[0], v[1]); upk2(acc2[jj][1], v[2], v[3]);
            upk2(acc2[jj][2], v[4], v[5]); upk2(acc2[jj][3], v[6], v[7]);
            float4* dst = (float4*)(P2u + (j0 + jj) * 128 + c0p);
            #pragma unroll
            for (int q = 0; q < 4; q++) {
                float p0 = fmaxf(v[2 * q], 0.f), p1 = fmaxf(v[2 * q + 1], 0.f);
                dst[q] = make_float4(p0, p0, p1, p1);
            }
        }
    }
    __syncthreads();

    // ---- phase 3: G1 = relu(P @ Wg1 + bg1) fused with Wg2 gate reduce ---
    // warp = rows 4w..4w+3; lanes 0..23 active: rr = l/8, m-cols m0..m0+7
    {
        int la = (l < 24) ? l : 23;
        int rr = la >> 3, m0 = (la & 7) * 8;
        const float* Wg = Wg1 + rr * (128 * 64) + m0;
        ull acc[4][4];
        {
            const ull* bg = (const ull*)(bg1 + rr * 64 + m0);
            #pragma unroll
            for (int jj = 0; jj < 4; jj++) {
                acc[jj][0] = bg[0]; acc[jj][1] = bg[1];
                acc[jj][2] = bg[2]; acc[jj][3] = bg[3];
            }
        }
        const ull* Prow = P2u + j0 * 128;
        #pragma unroll 4
        for (int h = 0; h < 128; h++) {
            ull w0, w1, w2, w3;
            ldg2x2(Wg + h * 64, w0, w1);
            ldg2x2(Wg + h * 64 + 4, w2, w3);
            #pragma unroll
            for (int jj = 0; jj < 4; jj++) {
                ull p = Prow[jj * 128 + h];
                fma2(acc[jj][0], p, w0); fma2(acc[jj][1], p, w1);
                fma2(acc[jj][2], p, w2); fma2(acc[jj][3], p, w3);
            }
        }
        float4 q0 = *(const float4*)(Wg2 + rr * 64 + m0);
        float4 q1 = *(const float4*)(Wg2 + rr * 64 + m0 + 4);
        float wq[8] = {q0.x,q0.y,q0.z,q0.w,q1.x,q1.y,q1.z,q1.w};
        float bgr = bg2[rr];
        #pragma unroll
        for (int jj = 0; jj < 4; jj++) {
            float v[8];
            upk2(acc[jj][0], v[0], v[1]); upk2(acc[jj][1], v[2], v[3]);
            upk2(acc[jj][2], v[4], v[5]); upk2(acc[jj][3], v[6], v[7]);
            float p = 0.f;
            #pragma unroll
            for (int i = 0; i < 8; i++) p += fmaxf(v[i], 0.f) * wq[i];
            p += __shfl_xor_sync(0xffffffffu, p, 1);
            p += __shfl_xor_sync(0xffffffffu, p, 2);
            p += __shfl_xor_sync(0xffffffffu, p, 4);
            if (l < 24 && (l & 7) == 0) {
                float gate = 1.f / (1.f + expf(-(p + bgr)));
                gpart[rr * 32 + j0 + jj] = gate * g_regime[rr];
            }
        }
    }
    __syncthreads();

    if (t < 32) {
        float gc = gpart[t] + gpart[32 + t] + gpart[64 + t];
        sc[t] = raw[t] * gc * g_amp;
    }
    __syncthreads();

    // ---- phase 5: dedupe (last wins), softmax, rank, top-k fill ---------
    if (t < 32) {
        int j = t;
        int tgj = tg[j];
        bool valid = true;
        for (int j2 = j + 1; j2 < 32; j2++)
            if (tg[j2] == tgj) valid = false;
        float sval = sc[j];
        float m = valid ? sval : -INFINITY;
        #pragma unroll
        for (int off = 16; off; off >>= 1)
            m = fmaxf(m, __shfl_xor_sync(0xffffffffu, m, off));
        float e = valid ? expf((sval - m) / TEMP) : 0.f;
        float sum = e;
        #pragma unroll
        for (int off = 16; off; off >>= 1)
            sum += __shfl_xor_sync(0xffffffffu, sum, off);
        float p = e / sum;

        unsigned vb = __ballot_sync(0xffffffffu, valid);
        int cnt = __popc(vb);
        int rank = 0;
        for (int j2 = 0; j2 < 32; j2++) {
            float p2 = __shfl_sync(0xffffffffu, p, j2);
            int  t2 = __shfl_sync(0xffffffffu, tgj, j2);
            bool v2 = (vb >> j2) & 1u;
            if (valid && v2 && j2 != j &&
                (p2 > p || (p2 == p && t2 < tgj))) rank++;
        }
        float* wout = out + (size_t)r * K_TOP;
        float* iout = out + (size_t)N_NODES * K_TOP + (size_t)r * K_TOP;
        if (valid) {
            wout[rank] = (p > THRESH) ? p : 0.f;
            if (write_idx) iout[rank] = (float)tgj;
        }
        if (j == 0 && cnt < 32) {
            int slot = cnt, v = 0;
            while (slot < 32) {
                bool member = false;
                for (int j2 = 0; j2 < 32; j2++)
                    if (((vb >> j2) & 1u) && tg[j2] == v) member = true;
                if (!member) {
                    wout[slot] = 0.f;
                    if (write_idx) iout[slot] = (float)v;
                    slot++;
                }
                v++;
            }
        }
    }
}

// ---------------------------------------------------------------------------
extern "C" void kernel_launch(void* const* d_in, const int* in_sizes, int n_in,
                              void* d_out, int out_size) {
    const float* x    = (const float*)d_in[0];
    const void*  eidx = d_in[1];
    const float* ea   = (const float*)d_in[2];
    const float* Ws1  = (const float*)d_in[3];
    const float* bs1  = (const float*)d_in[4];
    const float* ln_g = (const float*)d_in[5];
    const float* ln_b = (const float*)d_in[6];
    const float* Ws2  = (const float*)d_in[7];
    const float* bs2  = (const float*)d_in[8];
    const float* Wp   = (const float*)d_in[9];
    const float* bp   = (const float*)d_in[10];
    const float* Wr1  = (const float*)d_in[11];
    const float* br1  = (const float*)d_in[12];
    const float* Wr2  = (const float*)d_in[13];
    const float* br2  = (const float*)d_in[14];
    const float* Wg1  = (const float*)d_in[15];
    const float* bg1  = (const float*)d_in[16];
    const float* Wg2  = (const float*)d_in[17];
    const float* bg2  = (const float*)d_in[18];
    const float* Wc1  = (const float*)d_in[19];
    const float* bc1  = (const float*)d_in[20];
    const float* Wc2  = (const float*)d_in[21];
    const float* bc2  = (const float*)d_in[22];
    float* out = (float*)d_out;

    int write_idx = (out_size >= 2 * N_NODES * K_TOP) ? 1 : 0;

    cudaFuncSetAttribute(kB, cudaFuncAttributeMaxDynamicSharedMemorySize, SMEM_B_BYTES);

    kA1<<<A1_BLOCKS, 256>>>(x, Wc1, bc1, Wc2, bc2);
    kA2<<<1, 128>>>(Wr1, br1, Wr2, br2);
    kB<<<N_NODES, 256, SMEM_B_BYTES>>>(x, eidx, ea,
        Ws1, bs1, ln_g, ln_b, Ws2, bs2, Wp, bp,
        Wg1, bg1, Wg2, bg2, out, write_idx);
}

// round 8
// speedup vs baseline: 1.3180x; 1.3180x over previous
#include <cuda_runtime.h>
#include <math.h>

#define N_NODES 8192
#define F_DIM   64
#define H_DIM   128
#define R_DIM   3
#define DEG     32
#define K_TOP   32
#define E_EDGES (N_NODES*DEG)
#define TEMP    0.3f
#define NEG     0.2f
#define EPS_LN  1e-5f
#define THRESH  1e-6f

#define A1_BLOCKS 256

typedef unsigned long long ull;

// deterministic scratch (no atomics)
__device__ float g_part_gs[A1_BLOCKS * F_DIM];
__device__ float g_part_cont[A1_BLOCKS];
__device__ float g_regime[R_DIM];
__device__ float g_amp;

// ---------------------------------------------------------------------------
// f32x2 helpers
__device__ __forceinline__ ull pk2(float x, float y) {
    ull r;
    asm("mov.b64 %0, {%1, %2};" : "=l"(r) : "f"(x), "f"(y));
    return r;
}
__device__ __forceinline__ void upk2(ull v, float& x, float& y) {
    asm("mov.b64 {%0, %1}, %2;" : "=f"(x), "=f"(y) : "l"(v));
}
__device__ __forceinline__ void fma2(ull& d, ull a, ull b) {
    asm("fma.rn.f32x2 %0, %1, %2, %0;" : "+l"(d) : "l"(a), "l"(b));
}
// coalesced read-only 8B weight load (lane stride 2 floats -> 256B/warp)
__device__ __forceinline__ ull ldg64(const float* p) {
    ull r;
    asm("ld.global.nc.b64 %0, [%1];" : "=l"(r) : "l"(p));
    return r;
}

// ---------------------------------------------------------------------------
// A1: per-block (32 nodes) partial column sums of x, and partial contagion sums
__global__ void kA1(const float* __restrict__ x,
                    const float* __restrict__ Wc1, const float* __restrict__ bc1,
                    const float* __restrict__ Wc2, const float* __restrict__ bc2) {
    __shared__ float xs[32][64];
    __shared__ float colsum[4][64];
    __shared__ float cwarp[8];
    int t = threadIdx.x, b = blockIdx.x;
    int base = b * 32;
    for (int idx = t; idx < 32 * 64; idx += 256)
        xs[idx >> 6][idx & 63] = x[base * 64 + idx];
    __syncthreads();
    {
        int col = t & 63, g = t >> 6;
        float s = 0.f;
        #pragma unroll
        for (int rr = 0; rr < 8; rr++) s += xs[g * 8 + rr][col];
        colsum[g][col] = s;
    }
    int w = t >> 5, l = t & 31;
    float a[4][4];
    #pragma unroll
    for (int q = 0; q < 4; q++) {
        a[q][0] = bc1[l]; a[q][1] = bc1[l + 32];
        a[q][2] = bc1[l + 64]; a[q][3] = bc1[l + 96];
    }
    #pragma unroll 4
    for (int d = 0; d < 64; d++) {
        const float* Wd = Wc1 + d * 128;
        float w0 = Wd[l], w1 = Wd[l + 32], w2 = Wd[l + 64], w3 = Wd[l + 96];
        #pragma unroll
        for (int q = 0; q < 4; q++) {
            float xv = xs[w * 4 + q][d];
            a[q][0] += xv * w0; a[q][1] += xv * w1;
            a[q][2] += xv * w2; a[q][3] += xv * w3;
        }
    }
    float csum = 0.f;
    #pragma unroll
    for (int q = 0; q < 4; q++) {
        float s = fmaxf(a[q][0], 0.f) * Wc2[l]      + fmaxf(a[q][1], 0.f) * Wc2[l + 32]
                + fmaxf(a[q][2], 0.f) * Wc2[l + 64] + fmaxf(a[q][3], 0.f) * Wc2[l + 96];
        #pragma unroll
        for (int off = 16; off; off >>= 1) s += __shfl_xor_sync(0xffffffffu, s, off);
        if (l == 0) csum += 1.f / (1.f + expf(-(s + bc2[0])));
    }
    if (l == 0) cwarp[w] = csum;
    __syncthreads();
    if (t < 64) g_part_gs[b * 64 + t] = colsum[0][t] + colsum[1][t] + colsum[2][t] + colsum[3][t];
    if (t == 0) {
        float s = 0.f;
        for (int i = 0; i < 8; i++) s += cwarp[i];
        g_part_cont[b] = s;
    }
}

// ---------------------------------------------------------------------------
// A2: finalize gs mean, regime probs, contagion amp
__global__ void kA2(const float* __restrict__ Wr1, const float* __restrict__ br1,
                    const float* __restrict__ Wr2, const float* __restrict__ br2) {
    __shared__ float gs[64];
    __shared__ float hr[128];
    int t = threadIdx.x;
    if (t < 64) {
        float s = 0.f;
        for (int b = 0; b < A1_BLOCKS; b++) s += g_part_gs[b * 64 + t];
        gs[t] = s / (float)N_NODES;
    }
    __syncthreads();
    {
        float a = br1[t];
        for (int d = 0; d < 64; d++) a += gs[d] * Wr1[d * 128 + t];
        hr[t] = fmaxf(a, 0.f);
    }
    __syncthreads();
    if (t == 0) {
        float lg[3];
        for (int r = 0; r < 3; r++) {
            float a = br2[r];
            for (int h = 0; h < 128; h++) a += hr[h] * Wr2[h * 3 + r];
            lg[r] = a;
        }
        float m = fmaxf(lg[0], fmaxf(lg[1], lg[2]));
        float e0 = expf(lg[0] - m), e1 = expf(lg[1] - m), e2 = expf(lg[2] - m);
        float s = e0 + e1 + e2;
        g_regime[0] = e0 / s; g_regime[1] = e1 / s; g_regime[2] = e2 / s;
        float c = 0.f;
        for (int b = 0; b < A1_BLOCKS; b++) c += g_part_cont[b];
        g_amp = 1.f + 0.5f * (c / (float)N_NODES);
    }
}

// ---------------------------------------------------------------------------
// Main per-row kernel. Shared layout (float offsets):
//   [0:64)      sx            [64:96)   tg (int)     [96:192)  sea
//   [192:448)   base_f (fused 256 cols: 0..127 Ws1-side, 128..255 Wp-side)
//   [448:480)   raw           [480:512) sc           [512:608) gpart[3][32]
//   [608:4704)  A2 : 32 rows x 32 float4 {a,a,a',a'} (16 KB); Hs aliases after phase1
//   [4704:12896) P2 : 32 rows x 64 float4 {p,p,p',p'} (32 KB)
#define SM_A2    608
#define SM_P2    4704
#define SM_TOTAL 12896
#define SMEM_B_BYTES (SM_TOTAL * 4)

__global__ void __launch_bounds__(256, 4) kB(
    const float* __restrict__ x, const void* __restrict__ eidx, const float* __restrict__ ea,
    const float* __restrict__ Ws1, const float* __restrict__ bs1,
    const float* __restrict__ ln_g, const float* __restrict__ ln_b,
    const float* __restrict__ Ws2, const float* __restrict__ bs2,
    const float* __restrict__ Wp,  const float* __restrict__ bp,
    const float* __restrict__ Wg1, const float* __restrict__ bg1,
    const float* __restrict__ Wg2, const float* __restrict__ bg2,
    float* __restrict__ out, int write_idx) {

    extern __shared__ float smf[];
    float* sx     = smf;
    int*   tg     = (int*)(smf + 64);
    float* sea    = smf + 96;
    float* base_f = smf + 192;
    float* raw    = smf + 448;
    float* sc     = smf + 480;
    float* gpart  = smf + 512;
    float* A2     = smf + SM_A2;    // dup-pair float4, 2 d per float4
    float* Hs     = smf + SM_A2;    // aliases A2 after phase-1 mainloop
    float* P2     = smf + SM_P2;

    int t = threadIdx.x;
    int r = blockIdx.x;
    int w = t >> 5, l = t & 31;

    // ---- phase 0a: small loads -----------------------------------------
    if (t < 16) ((float4*)sx)[t] = ((const float4*)(x + r * 64))[t];
    if (t >= 64 && t < 96) {
        int j = t - 64;
        int e = r * DEG + j;
        const long long* p64 = (const long long*)eidx;
        int tgv;
        if (p64[32] == 1LL) tgv = (int)p64[E_EDGES + e];
        else                tgv = ((const int*)eidx)[E_EDGES + e];
        tg[j] = tgv;
    }
    if (t >= 96 && t < 192) sea[t - 96] = ea[r * 96 + (t - 96)];
    __syncthreads();

    // ---- phase 0b: base_f (t<64) | gather A2 duplicated (t>=64) ---------
    if (t < 64) {
        int c0 = 4 * t;  // fused column
        const float* W = (t < 32) ? (Ws1 + c0) : (Wp + (c0 - 128));
        float4 acc = (t < 32) ? *(const float4*)(bs1 + c0) : *(const float4*)(bp + (c0 - 128));
        #pragma unroll 4
        for (int d = 0; d < 64; d++) {
            float4 w4 = *(const float4*)(W + d * 128);
            float a = sx[d];
            acc.x += a * w4.x; acc.y += a * w4.y; acc.z += a * w4.z; acc.w += a * w4.w;
        }
        ((float4*)base_f)[t] = acc;
    } else {
        const float4* x4 = (const float4*)x;
        float4* A4w = (float4*)A2;
        for (int idx = t - 64; idx < 512; idx += 192) {
            int row = idx >> 4, d4 = idx & 15;
            float4 v = x4[tg[row] * 16 + d4];
            A4w[row * 32 + d4 * 2 + 0] = make_float4(v.x, v.x, v.y, v.y);
            A4w[row * 32 + d4 * 2 + 1] = make_float4(v.z, v.z, v.w, v.w);
        }
    }
    __syncthreads();

    // ---- phase 1: fused [32 x 256] GEMM (H | P), col-pair per lane ------
    // warp w: rowhalf = w>>2, matsel = (w>>1)&1 (0=H,1=P), colgrp = w&1
    // lane -> col-pair c2 = colgrp*32 + l, cols 2c2, 2c2+1; 16 rows each.
    int rowhalf = w >> 2, matsel = (w >> 1) & 1, colgrp = w & 1;
    int c2 = colgrp * 32 + l;
    int rowbase = rowhalf * 16;
    const float* Wmat = matsel ? Wp : Ws1;
    const float* Wtgt = Wmat + 64 * 128 + 2 * c2;
    ull acc[16];
    {
        ull bval = ((const ull*)base_f)[matsel * 64 + c2];
        #pragma unroll
        for (int jj = 0; jj < 16; jj++) acc[jj] = bval;
    }
    {
        const ulonglong2* Arow = (const ulonglong2*)A2 + rowbase * 32;
        #pragma unroll 2
        for (int d2 = 0; d2 < 32; d2++) {
            ull w0 = ldg64(Wtgt + (2 * d2) * 128);
            ull w1 = ldg64(Wtgt + (2 * d2 + 1) * 128);
            #pragma unroll
            for (int jj = 0; jj < 16; jj++) {
                ulonglong2 av = Arow[jj * 32 + d2];
                fma2(acc[jj], av.x, w0);
                fma2(acc[jj], av.y, w1);
            }
        }
        // edge-attr tail (rows 128..130 of the fused weight)
        #pragma unroll
        for (int k = 0; k < 3; k++) {
            ull ek = ldg64(Wmat + (128 + k) * 128 + 2 * c2);
            #pragma unroll
            for (int jj = 0; jj < 16; jj++) {
                float sv = sea[(rowbase + jj) * 3 + k];
                fma2(acc[jj], pk2(sv, sv), ek);
            }
        }
    }
    __syncthreads();   // A2 reads done everywhere; Hs may now alias it

    // ---- phase 1 epilogue ----------------------------------------------
    if (matsel == 0) {
        // H: raw store for LayerNorm phase
        #pragma unroll
        for (int jj = 0; jj < 16; jj++)
            *(ull*)(Hs + (rowbase + jj) * 128 + 2 * c2) = acc[jj];
    } else {
        // P: relu + duplicated-pair store
        float4* P4 = (float4*)P2;
        #pragma unroll
        for (int jj = 0; jj < 16; jj++) {
            float p0, p1;
            upk2(acc[jj], p0, p1);
            p0 = fmaxf(p0, 0.f); p1 = fmaxf(p1, 0.f);
            P4[(rowbase + jj) * 64 + c2] = make_float4(p0, p0, p1, p1);
        }
    }
    __syncthreads();

    // ---- phase 2: LayerNorm + LeakyReLU + score_raw (warp per 4 rows) ---
    {
        float bias2 = bs2[0];
        for (int q = 0; q < 4; q++) {
            int j = w * 4 + q;
            const float* hj = Hs + j * 128;
            float v0 = hj[l], v1 = hj[l + 32], v2 = hj[l + 64], v3 = hj[l + 96];
            float s  = v0 + v1 + v2 + v3;
            float ss = v0 * v0 + v1 * v1 + v2 * v2 + v3 * v3;
            #pragma unroll
            for (int off = 16; off; off >>= 1) {
                s  += __shfl_xor_sync(0xffffffffu, s, off);
                ss += __shfl_xor_sync(0xffffffffu, ss, off);
            }
            float mu  = s * (1.f / 128.f);
            float var = fmaxf(ss * (1.f / 128.f) - mu * mu, 0.f);
            float inv = rsqrtf(var + EPS_LN);
            float vv[4] = {v0, v1, v2, v3};
            float contrib = 0.f;
            #pragma unroll
            for (int k4 = 0; k4 < 4; k4++) {
                int hh = l + 32 * k4;
                float hn = (vv[k4] - mu) * inv * ln_g[hh] + ln_b[hh];
                hn = hn >= 0.f ? hn : NEG * hn;
                contrib += hn * Ws2[hh];
            }
            #pragma unroll
            for (int off = 16; off; off >>= 1)
                contrib += __shfl_xor_sync(0xffffffffu, contrib, off);
            if (l == 0) raw[j] = contrib + bias2;
        }
    }

    // ---- phase 3: G1 = relu(P @ Wg1 + bg1) fused with Wg2 reduce --------
    // warps 0..5: rr = w>>1, rowhalf3 = w&1; lane = m-pair (cols 2l,2l+1 of 64)
    if (w < 6) {
        int rr = w >> 1, rb3 = (w & 1) * 16;
        const float* Wg = Wg1 + rr * (128 * 64) + 2 * l;
        ull acc3[16];
        {
            ull bgv = *(const ull*)(bg1 + rr * 64 + 2 * l);
            #pragma unroll
            for (int jj = 0; jj < 16; jj++) acc3[jj] = bgv;
        }
        const ulonglong2* Prow = (const ulonglong2*)P2 + rb3 * 64;
        #pragma unroll 2
        for (int h2 = 0; h2 < 64; h2++) {
            ull w0 = ldg64(Wg + (2 * h2) * 64);
            ull w1 = ldg64(Wg + (2 * h2 + 1) * 64);
            #pragma unroll
            for (int jj = 0; jj < 16; jj++) {
                ulonglong2 pv = Prow[jj * 64 + h2];
                fma2(acc3[jj], pv.x, w0);
                fma2(acc3[jj], pv.y, w1);
            }
        }
        float2 wq = *(const float2*)(Wg2 + rr * 64 + 2 * l);
        float bgr = bg2[rr];
        float reg = g_regime[rr];
        #pragma unroll
        for (int jj = 0; jj < 16; jj++) {
            float v0, v1;
            upk2(acc3[jj], v0, v1);
            float s = fmaxf(v0, 0.f) * wq.x + fmaxf(v1, 0.f) * wq.y;
            #pragma unroll
            for (int off = 16; off; off >>= 1)
                s += __shfl_xor_sync(0xffffffffu, s, off);
            if (l == 0) {
                float gate = 1.f / (1.f + expf(-(s + bgr)));
                gpart[rr * 32 + rb3 + jj] = gate * reg;
            }
        }
    }
    __syncthreads();

    if (t < 32) {
        float gc = gpart[t] + gpart[32 + t] + gpart[64 + t];
        sc[t] = raw[t] * gc * g_amp;
    }
    __syncthreads();

    // ---- phase 5: dedupe (last wins), softmax, rank, top-k fill ---------
    if (t < 32) {
        int j = t;
        int tgj = tg[j];
        bool valid = true;
        for (int j2 = j + 1; j2 < 32; j2++)
            if (tg[j2] == tgj) valid = false;
        float sval = sc[j];
        float m = valid ? sval : -INFINITY;
        #pragma unroll
        for (int off = 16; off; off >>= 1)
            m = fmaxf(m, __shfl_xor_sync(0xffffffffu, m, off));
        float e = valid ? expf((sval - m) / TEMP) : 0.f;
        float sum = e;
        #pragma unroll
        for (int off = 16; off; off >>= 1)
            sum += __shfl_xor_sync(0xffffffffu, sum, off);
        float p = e / sum;

        unsigned vb = __ballot_sync(0xffffffffu, valid);
        int cnt = __popc(vb);
        int rank = 0;
        for (int j2 = 0; j2 < 32; j2++) {
            float p2 = __shfl_sync(0xffffffffu, p, j2);
            int  t2 = __shfl_sync(0xffffffffu, tgj, j2);
            bool v2 = (vb >> j2) & 1u;
            if (valid && v2 && j2 != j &&
                (p2 > p || (p2 == p && t2 < tgj))) rank++;
        }
        float* wout = out + (size_t)r * K_TOP;
        float* iout = out + (size_t)N_NODES * K_TOP + (size_t)r * K_TOP;
        if (valid) {
            wout[rank] = (p > THRESH) ? p : 0.f;
            if (write_idx) iout[rank] = (float)tgj;
        }
        if (j == 0 && cnt < 32) {
            int slot = cnt, v = 0;
            while (slot < 32) {
                bool member = false;
                for (int j2 = 0; j2 < 32; j2++)
                    if (((vb >> j2) & 1u) && tg[j2] == v) member = true;
                if (!member) {
                    wout[slot] = 0.f;
                    if (write_idx) iout[slot] = (float)v;
                    slot++;
                }
                v++;
            }
        }
    }
}

// ---------------------------------------------------------------------------
extern "C" void kernel_launch(void* const* d_in, const int* in_sizes, int n_in,
                              void* d_out, int out_size) {
    const float* x    = (const float*)d_in[0];
    const void*  eidx = d_in[1];
    const float* ea   = (const float*)d_in[2];
    const float* Ws1  = (const float*)d_in[3];
    const float* bs1  = (const float*)d_in[4];
    const float* ln_g = (const float*)d_in[5];
    const float* ln_b = (const float*)d_in[6];
    const float* Ws2  = (const float*)d_in[7];
    const float* bs2  = (const float*)d_in[8];
    const float* Wp   = (const float*)d_in[9];
    const float* bp   = (const float*)d_in[10];
    const float* Wr1  = (const float*)d_in[11];
    const float* br1  = (const float*)d_in[12];
    const float* Wr2  = (const float*)d_in[13];
    const float* br2  = (const float*)d_in[14];
    const float* Wg1  = (const float*)d_in[15];
    const float* bg1  = (const float*)d_in[16];
    const float* Wg2  = (const float*)d_in[17];
    const float* bg2  = (const float*)d_in[18];
    const float* Wc1  = (const float*)d_in[19];
    const float* bc1  = (const float*)d_in[20];
    const float* Wc2  = (const float*)d_in[21];
    const float* bc2  = (const float*)d_in[22];
    float* out = (float*)d_out;

    int write_idx = (out_size >= 2 * N_NODES * K_TOP) ? 1 : 0;

    cudaFuncSetAttribute(kB, cudaFuncAttributeMaxDynamicSharedMemorySize, SMEM_B_BYTES);

    kA1<<<A1_BLOCKS, 256>>>(x, Wc1, bc1, Wc2, bc2);
    kA2<<<1, 128>>>(Wr1, br1, Wr2, br2);
    kB<<<N_NODES, 256, SMEM_B_BYTES>>>(x, eidx, ea,
        Ws1, bs1, ln_g, ln_b, Ws2, bs2, Wp, bp,
        Wg1, bg1, Wg2, bg2, out, write_idx);
}

// round 9
// speedup vs baseline: 1.5863x; 1.2035x over previous
#include <cuda_runtime.h>
#include <math.h>

#define N_NODES 8192
#define F_DIM   64
#define H_DIM   128
#define R_DIM   3
#define DEG     32
#define K_TOP   32
#define E_EDGES (N_NODES*DEG)
#define TEMP    0.3f
#define NEG     0.2f
#define EPS_LN  1e-5f
#define THRESH  1e-6f

#define A1_BLOCKS 256

typedef unsigned long long ull;

// deterministic scratch (no atomics)
__device__ float g_part_gs[A1_BLOCKS * F_DIM];
__device__ float g_part_cont[A1_BLOCKS];
__device__ float g_regime[R_DIM];
__device__ float g_amp;

// ---------------------------------------------------------------------------
// f32x2 helpers
__device__ __forceinline__ ull pk2(float x, float y) {
    ull r;
    asm("mov.b64 %0, {%1, %2};" : "=l"(r) : "f"(x), "f"(y));
    return r;
}
__device__ __forceinline__ void upk2(ull v, float& x, float& y) {
    asm("mov.b64 {%0, %1}, %2;" : "=f"(x), "=f"(y) : "l"(v));
}
__device__ __forceinline__ void fma2(ull& d, ull a, ull b) {
    asm("fma.rn.f32x2 %0, %1, %2, %0;" : "+l"(d) : "l"(a), "l"(b));
}
// coalesced read-only 8B weight load (lane stride 2 floats -> 256B/warp)
__device__ __forceinline__ ull ldg64(const float* p) {
    ull r;
    asm("ld.global.nc.b64 %0, [%1];" : "=l"(r) : "l"(p));
    return r;
}

// ---------------------------------------------------------------------------
// A1: per-block (32 nodes) partial column sums of x, and partial contagion sums
__global__ void kA1(const float* __restrict__ x,
                    const float* __restrict__ Wc1, const float* __restrict__ bc1,
                    const float* __restrict__ Wc2, const float* __restrict__ bc2) {
    __shared__ float xs[32][64];
    __shared__ float colsum[4][64];
    __shared__ float cwarp[8];
    int t = threadIdx.x, b = blockIdx.x;
    int base = b * 32;
    for (int idx = t; idx < 32 * 64; idx += 256)
        xs[idx >> 6][idx & 63] = x[base * 64 + idx];
    __syncthreads();
    {
        int col = t & 63, g = t >> 6;
        float s = 0.f;
        #pragma unroll
        for (int rr = 0; rr < 8; rr++) s += xs[g * 8 + rr][col];
        colsum[g][col] = s;
    }
    int w = t >> 5, l = t & 31;
    float a[4][4];
    #pragma unroll
    for (int q = 0; q < 4; q++) {
        a[q][0] = bc1[l]; a[q][1] = bc1[l + 32];
        a[q][2] = bc1[l + 64]; a[q][3] = bc1[l + 96];
    }
    #pragma unroll 4
    for (int d = 0; d < 64; d++) {
        const float* Wd = Wc1 + d * 128;
        float w0 = Wd[l], w1 = Wd[l + 32], w2 = Wd[l + 64], w3 = Wd[l + 96];
        #pragma unroll
        for (int q = 0; q < 4; q++) {
            float xv = xs[w * 4 + q][d];
            a[q][0] += xv * w0; a[q][1] += xv * w1;
            a[q][2] += xv * w2; a[q][3] += xv * w3;
        }
    }
    float csum = 0.f;
    #pragma unroll
    for (int q = 0; q < 4; q++) {
        float s = fmaxf(a[q][0], 0.f) * Wc2[l]      + fmaxf(a[q][1], 0.f) * Wc2[l + 32]
                + fmaxf(a[q][2], 0.f) * Wc2[l + 64] + fmaxf(a[q][3], 0.f) * Wc2[l + 96];
        #pragma unroll
        for (int off = 16; off; off >>= 1) s += __shfl_xor_sync(0xffffffffu, s, off);
        if (l == 0) csum += 1.f / (1.f + expf(-(s + bc2[0])));
    }
    if (l == 0) cwarp[w] = csum;
    __syncthreads();
    if (t < 64) g_part_gs[b * 64 + t] = colsum[0][t] + colsum[1][t] + colsum[2][t] + colsum[3][t];
    if (t == 0) {
        float s = 0.f;
        for (int i = 0; i < 8; i++) s += cwarp[i];
        g_part_cont[b] = s;
    }
}

// ---------------------------------------------------------------------------
// A2: finalize gs mean, regime probs, contagion amp
__global__ void kA2(const float* __restrict__ Wr1, const float* __restrict__ br1,
                    const float* __restrict__ Wr2, const float* __restrict__ br2) {
    __shared__ float gs[64];
    __shared__ float hr[128];
    int t = threadIdx.x;
    if (t < 64) {
        float s = 0.f;
        for (int b = 0; b < A1_BLOCKS; b++) s += g_part_gs[b * 64 + t];
        gs[t] = s / (float)N_NODES;
    }
    __syncthreads();
    {
        float a = br1[t];
        for (int d = 0; d < 64; d++) a += gs[d] * Wr1[d * 128 + t];
        hr[t] = fmaxf(a, 0.f);
    }
    __syncthreads();
    if (t == 0) {
        float lg[3];
        for (int r = 0; r < 3; r++) {
            float a = br2[r];
            for (int h = 0; h < 128; h++) a += hr[h] * Wr2[h * 3 + r];
            lg[r] = a;
        }
        float m = fmaxf(lg[0], fmaxf(lg[1], lg[2]));
        float e0 = expf(lg[0] - m), e1 = expf(lg[1] - m), e2 = expf(lg[2] - m);
        float s = e0 + e1 + e2;
        g_regime[0] = e0 / s; g_regime[1] = e1 / s; g_regime[2] = e2 / s;
        float c = 0.f;
        for (int b = 0; b < A1_BLOCKS; b++) c += g_part_cont[b];
        g_amp = 1.f + 0.5f * (c / (float)N_NODES);
    }
}

// ---------------------------------------------------------------------------
// Main per-row kernel. Shared layout (float offsets):
//   [0:64)      sx            [64:96)   tg (int)     [96:192)  sea
//   [192:448)   base_f        [448:480) raw          [480:512) sc
//   [512:608)   gpart[3][32]
//   [608:4704)  A2 : 32 rows x 32 float4 {a,a,a',a'} (16 KB); Hs aliases after phase1
//   [4704:8800) P2 : 32 rows x 128 floats plain (16 KB)
#define SM_A2    608
#define SM_P2    4704
#define SM_TOTAL 8800
#define SMEM_B_BYTES (SM_TOTAL * 4)

__global__ void __launch_bounds__(256, 3) kB(
    const float* __restrict__ x, const void* __restrict__ eidx, const float* __restrict__ ea,
    const float* __restrict__ Ws1, const float* __restrict__ bs1,
    const float* __restrict__ ln_g, const float* __restrict__ ln_b,
    const float* __restrict__ Ws2, const float* __restrict__ bs2,
    const float* __restrict__ Wp,  const float* __restrict__ bp,
    const float* __restrict__ Wg1, const float* __restrict__ bg1,
    const float* __restrict__ Wg2, const float* __restrict__ bg2,
    float* __restrict__ out, int write_idx) {

    extern __shared__ float smf[];
    float* sx     = smf;
    int*   tg     = (int*)(smf + 64);
    float* sea    = smf + 96;
    float* base_f = smf + 192;
    float* raw    = smf + 448;
    float* sc     = smf + 480;
    float* gpart  = smf + 512;
    float* A2     = smf + SM_A2;    // dup-pair float4, 2 d per float4
    float* Hs     = smf + SM_A2;    // aliases A2 after phase-1 mainloop
    float* P2     = smf + SM_P2;    // plain [32][128]

    int t = threadIdx.x;
    int r = blockIdx.x;
    int w = t >> 5, l = t & 31;

    // ---- phase 0a: small loads -----------------------------------------
    if (t < 16) ((float4*)sx)[t] = ((const float4*)(x + r * 64))[t];
    if (t >= 64 && t < 96) {
        int j = t - 64;
        int e = r * DEG + j;
        const long long* p64 = (const long long*)eidx;
        int tgv;
        if (p64[32] == 1LL) tgv = (int)p64[E_EDGES + e];
        else                tgv = ((const int*)eidx)[E_EDGES + e];
        tg[j] = tgv;
    }
    if (t >= 96 && t < 192) sea[t - 96] = ea[r * 96 + (t - 96)];
    __syncthreads();

    // ---- phase 0b: base_f (t<64) | gather A2 duplicated (t>=64) ---------
    if (t < 64) {
        int c0 = 4 * t;  // fused column
        const float* W = (t < 32) ? (Ws1 + c0) : (Wp + (c0 - 128));
        float4 acc = (t < 32) ? *(const float4*)(bs1 + c0) : *(const float4*)(bp + (c0 - 128));
        #pragma unroll 4
        for (int d = 0; d < 64; d++) {
            float4 w4 = *(const float4*)(W + d * 128);
            float a = sx[d];
            acc.x += a * w4.x; acc.y += a * w4.y; acc.z += a * w4.z; acc.w += a * w4.w;
        }
        ((float4*)base_f)[t] = acc;
    } else {
        const float4* x4 = (const float4*)x;
        float4* A4w = (float4*)A2;
        for (int idx = t - 64; idx < 512; idx += 192) {
            int row = idx >> 4, d4 = idx & 15;
            float4 v = x4[tg[row] * 16 + d4];
            A4w[row * 32 + d4 * 2 + 0] = make_float4(v.x, v.x, v.y, v.y);
            A4w[row * 32 + d4 * 2 + 1] = make_float4(v.z, v.z, v.w, v.w);
        }
    }
    __syncthreads();

    // ---- phase 1: fused [32 x 256] GEMM (H | P), col-pair per lane ------
    // warp w: rowhalf = w>>2, matsel = (w>>1)&1 (0=H,1=P), colgrp = w&1
    int rowhalf = w >> 2, matsel = (w >> 1) & 1, colgrp = w & 1;
    int c2 = colgrp * 32 + l;
    int rowbase = rowhalf * 16;
    const float* Wmat = matsel ? Wp : Ws1;
    const float* Wtgt = Wmat + 64 * 128 + 2 * c2;
    ull acc[16];
    {
        ull bval = ((const ull*)base_f)[matsel * 64 + c2];
        #pragma unroll
        for (int jj = 0; jj < 16; jj++) acc[jj] = bval;
    }
    {
        const ulonglong2* Arow = (const ulonglong2*)A2 + rowbase * 32;
        #pragma unroll 2
        for (int d2 = 0; d2 < 32; d2++) {
            ull w0 = ldg64(Wtgt + (2 * d2) * 128);
            ull w1 = ldg64(Wtgt + (2 * d2 + 1) * 128);
            #pragma unroll
            for (int jj = 0; jj < 16; jj++) {
                ulonglong2 av = Arow[jj * 32 + d2];
                fma2(acc[jj], av.x, w0);
                fma2(acc[jj], av.y, w1);
            }
        }
        // edge-attr tail (rows 128..130 of the fused weight)
        #pragma unroll
        for (int k = 0; k < 3; k++) {
            ull ek = ldg64(Wmat + (128 + k) * 128 + 2 * c2);
            #pragma unroll
            for (int jj = 0; jj < 16; jj++) {
                float sv = sea[(rowbase + jj) * 3 + k];
                fma2(acc[jj], pk2(sv, sv), ek);
            }
        }
    }
    __syncthreads();   // A2 reads done everywhere; Hs may now alias it

    // ---- phase 1 epilogue ----------------------------------------------
    if (matsel == 0) {
        // H: raw store for LayerNorm phase
        #pragma unroll
        for (int jj = 0; jj < 16; jj++)
            *(ull*)(Hs + (rowbase + jj) * 128 + 2 * c2) = acc[jj];
    } else {
        // P: relu + plain float2 store
        #pragma unroll
        for (int jj = 0; jj < 16; jj++) {
            float p0, p1;
            upk2(acc[jj], p0, p1);
            p0 = fmaxf(p0, 0.f); p1 = fmaxf(p1, 0.f);
            *(float2*)(P2 + (rowbase + jj) * 128 + 2 * c2) = make_float2(p0, p1);
        }
    }
    __syncthreads();

    // ---- phase 2: LayerNorm + LeakyReLU + score_raw (warp per 4 rows) ---
    {
        float bias2 = bs2[0];
        for (int q = 0; q < 4; q++) {
            int j = w * 4 + q;
            const float* hj = Hs + j * 128;
            float v0 = hj[l], v1 = hj[l + 32], v2 = hj[l + 64], v3 = hj[l + 96];
            float s  = v0 + v1 + v2 + v3;
            float ss = v0 * v0 + v1 * v1 + v2 * v2 + v3 * v3;
            #pragma unroll
            for (int off = 16; off; off >>= 1) {
                s  += __shfl_xor_sync(0xffffffffu, s, off);
                ss += __shfl_xor_sync(0xffffffffu, ss, off);
            }
            float mu  = s * (1.f / 128.f);
            float var = fmaxf(ss * (1.f / 128.f) - mu * mu, 0.f);
            float inv = rsqrtf(var + EPS_LN);
            float vv[4] = {v0, v1, v2, v3};
            float contrib = 0.f;
            #pragma unroll
            for (int k4 = 0; k4 < 4; k4++) {
                int hh = l + 32 * k4;
                float hn = (vv[k4] - mu) * inv * ln_g[hh] + ln_b[hh];
                hn = hn >= 0.f ? hn : NEG * hn;
                contrib += hn * Ws2[hh];
            }
            #pragma unroll
            for (int off = 16; off; off >>= 1)
                contrib += __shfl_xor_sync(0xffffffffu, contrib, off);
            if (l == 0) raw[j] = contrib + bias2;
        }
    }

    // ---- phase 3: G1 = relu(P @ Wg1 + bg1) fused with Wg2 reduce --------
    // ALL 8 warps: warp w -> rows 4w..4w+3, all 3 regimes internally.
    // lane l -> m-cols 2l, 2l+1.
    {
        ull acc3[3][4];
        #pragma unroll
        for (int rr = 0; rr < 3; rr++) {
            ull bgv = *(const ull*)(bg1 + rr * 64 + 2 * l);
            #pragma unroll
            for (int q = 0; q < 4; q++) acc3[rr][q] = bgv;
        }
        const float* Prow = P2 + (4 * w) * 128;
        #pragma unroll 2
        for (int h4 = 0; h4 < 32; h4++) {
            // 4 rows x 4 h-values, packed once, reused across 3 regimes
            ull pp[4][4];
            #pragma unroll
            for (int q = 0; q < 4; q++) {
                float4 pv = ((const float4*)(Prow + q * 128))[h4];
                pp[q][0] = pk2(pv.x, pv.x); pp[q][1] = pk2(pv.y, pv.y);
                pp[q][2] = pk2(pv.z, pv.z); pp[q][3] = pk2(pv.w, pv.w);
            }
            #pragma unroll
            for (int rr = 0; rr < 3; rr++) {
                const float* Wg = Wg1 + rr * (128 * 64) + 2 * l;
                ull w0 = ldg64(Wg + (4 * h4 + 0) * 64);
                ull w1 = ldg64(Wg + (4 * h4 + 1) * 64);
                ull w2 = ldg64(Wg + (4 * h4 + 2) * 64);
                ull w3 = ldg64(Wg + (4 * h4 + 3) * 64);
                #pragma unroll
                for (int q = 0; q < 4; q++) {
                    fma2(acc3[rr][q], pp[q][0], w0);
                    fma2(acc3[rr][q], pp[q][1], w1);
                    fma2(acc3[rr][q], pp[q][2], w2);
                    fma2(acc3[rr][q], pp[q][3], w3);
                }
            }
        }
        #pragma unroll
        for (int rr = 0; rr < 3; rr++) {
            float2 wq = *(const float2*)(Wg2 + rr * 64 + 2 * l);
            float bgr = bg2[rr];
            float reg = g_regime[rr];
            #pragma unroll
            for (int q = 0; q < 4; q++) {
                float v0, v1;
                upk2(acc3[rr][q], v0, v1);
                float s = fmaxf(v0, 0.f) * wq.x + fmaxf(v1, 0.f) * wq.y;
                #pragma unroll
                for (int off = 16; off; off >>= 1)
                    s += __shfl_xor_sync(0xffffffffu, s, off);
                if (l == 0) {
                    float gate = 1.f / (1.f + expf(-(s + bgr)));
                    gpart[rr * 32 + 4 * w + q] = gate * reg;
                }
            }
        }
    }
    __syncthreads();

    if (t < 32) {
        float gc = gpart[t] + gpart[32 + t] + gpart[64 + t];
        sc[t] = raw[t] * gc * g_amp;
    }
    __syncthreads();

    // ---- phase 5: dedupe (last wins), softmax, rank, top-k fill ---------
    if (t < 32) {
        int j = t;
        int tgj = tg[j];
        bool valid = true;
        for (int j2 = j + 1; j2 < 32; j2++)
            if (tg[j2] == tgj) valid = false;
        float sval = sc[j];
        float m = valid ? sval : -INFINITY;
        #pragma unroll
        for (int off = 16; off; off >>= 1)
            m = fmaxf(m, __shfl_xor_sync(0xffffffffu, m, off));
        float e = valid ? expf((sval - m) / TEMP) : 0.f;
        float sum = e;
        #pragma unroll
        for (int off = 16; off; off >>= 1)
            sum += __shfl_xor_sync(0xffffffffu, sum, off);
        float p = e / sum;

        unsigned vb = __ballot_sync(0xffffffffu, valid);
        int cnt = __popc(vb);
        int rank = 0;
        for (int j2 = 0; j2 < 32; j2++) {
            float p2 = __shfl_sync(0xffffffffu, p, j2);
            int  t2 = __shfl_sync(0xffffffffu, tgj, j2);
            bool v2 = (vb >> j2) & 1u;
            if (valid && v2 && j2 != j &&
                (p2 > p || (p2 == p && t2 < tgj))) rank++;
        }
        float* wout = out + (size_t)r * K_TOP;
        float* iout = out + (size_t)N_NODES * K_TOP + (size_t)r * K_TOP;
        if (valid) {
            wout[rank] = (p > THRESH) ? p : 0.f;
            if (write_idx) iout[rank] = (float)tgj;
        }
        if (j == 0 && cnt < 32) {
            int slot = cnt, v = 0;
            while (slot < 32) {
                bool member = false;
                for (int j2 = 0; j2 < 32; j2++)
                    if (((vb >> j2) & 1u) && tg[j2] == v) member = true;
                if (!member) {
                    wout[slot] = 0.f;
                    if (write_idx) iout[slot] = (float)v;
                    slot++;
                }
                v++;
            }
        }
    }
}

// ---------------------------------------------------------------------------
extern "C" void kernel_launch(void* const* d_in, const int* in_sizes, int n_in,
                              void* d_out, int out_size) {
    const float* x    = (const float*)d_in[0];
    const void*  eidx = d_in[1];
    const float* ea   = (const float*)d_in[2];
    const float* Ws1  = (const float*)d_in[3];
    const float* bs1  = (const float*)d_in[4];
    const float* ln_g = (const float*)d_in[5];
    const float* ln_b = (const float*)d_in[6];
    const float* Ws2  = (const float*)d_in[7];
    const float* bs2  = (const float*)d_in[8];
    const float* Wp   = (const float*)d_in[9];
    const float* bp   = (const float*)d_in[10];
    const float* Wr1  = (const float*)d_in[11];
    const float* br1  = (const float*)d_in[12];
    const float* Wr2  = (const float*)d_in[13];
    const float* br2  = (const float*)d_in[14];
    const float* Wg1  = (const float*)d_in[15];
    const float* bg1  = (const float*)d_in[16];
    const float* Wg2  = (const float*)d_in[17];
    const float* bg2  = (const float*)d_in[18];
    const float* Wc1  = (const float*)d_in[19];
    const float* bc1  = (const float*)d_in[20];
    const float* Wc2  = (const float*)d_in[21];
    const float* bc2  = (const float*)d_in[22];
    float* out = (float*)d_out;

    int write_idx = (out_size >= 2 * N_NODES * K_TOP) ? 1 : 0;

    cudaFuncSetAttribute(kB, cudaFuncAttributeMaxDynamicSharedMemorySize, SMEM_B_BYTES);

    kA1<<<A1_BLOCKS, 256>>>(x, Wc1, bc1, Wc2, bc2);
    kA2<<<1, 128>>>(Wr1, br1, Wr2, br2);
    kB<<<N_NODES, 256, SMEM_B_BYTES>>>(x, eidx, ea,
        Ws1, bs1, ln_g, ln_b, Ws2, bs2, Wp, bp,
        Wg1, bg1, Wg2, bg2, out, write_idx);
}